// round 9
// baseline (speedup 1.0000x reference)
#include <cuda_runtime.h>
#include <cuda_bf16.h>
#include <cstdint>
#include <cstddef>

typedef unsigned long long ull;

#define BB 512
#define TT 1024
#define INDIM 32
#define HH 128
#define GG 512            // 4*H
#define DLL 256
#define OUTD 32
#define M_TOT (BB*TT)     // 524288

// ---- lstm smem: weights 49152 floats + h double-buffer 1024 floats ----
#define KPSM 48
#define LSTM_SMEM ((49152 + 1024) * 4)    // 200704 bytes

// -------- device scratch (static; no runtime allocation) --------
__device__ float g_xg[(size_t)M_TOT * GG];
__device__ float g_h0[(size_t)M_TOT * HH];
__device__ float g_hlast[BB * HH];
__device__ float g_WT0[HH * GG];
__device__ float g_WT1[HH * GG];

// ---------------- f32x2 helpers ----------------
__device__ __forceinline__ ull fma2(ull a, ull b, ull c) {
    ull d;
    asm("fma.rn.f32x2 %0, %1, %2, %3;" : "=l"(d) : "l"(a), "l"(b), "l"(c));
    return d;
}
__device__ __forceinline__ ull add2(ull a, ull b) {
    ull d;
    asm("add.rn.f32x2 %0, %1, %2;" : "=l"(d) : "l"(a), "l"(b));
    return d;
}
__device__ __forceinline__ void unpack2(ull v, float& x, float& y) {
    unsigned a, b;
    asm("mov.b64 {%0, %1}, %2;" : "=r"(a), "=r"(b) : "l"(v));
    x = __uint_as_float(a);
    y = __uint_as_float(b);
}
__device__ __forceinline__ float red2(ull v) {
    float a, b;
    unpack2(v, a, b);
    return a + b;
}
__device__ __forceinline__ float sigf(float x)  { return __fdividef(1.0f, 1.0f + __expf(-x)); }
__device__ __forceinline__ float tanhx(float x) { return __fdividef(2.0f, 1.0f + __expf(-2.0f * x)) - 1.0f; }

// -------- interleave Whh for lstm (unchanged layout) --------
__global__ void prep_whh(const float* __restrict__ W, float* __restrict__ WTI) {
    int idx = blockIdx.x * 256 + threadIdx.x;
    if (idx < HH * GG) {
        int r = idx >> 15;
        int rem = idx & 32767;
        int kp = rem >> 9;
        int rem2 = rem & 511;
        int j = rem2 >> 2;
        int t = rem2 & 3;
        int qq = t >> 1;
        int e = t & 1;
        int q = r * 2 + qq;
        WTI[idx] = W[(q * HH + j) * HH + 2 * kp + e];
    }
}

// ================= mma.sync bf16 hi/lo pre-gate GEMM (round-7 proven) =================
#define MMA_BF16(D, A0, A1, A2, A3, B0, B1) \
    asm volatile( \
        "mma.sync.aligned.m16n8k16.row.col.f32.bf16.bf16.f32 " \
        "{%0,%1,%2,%3}, {%4,%5,%6,%7}, {%8,%9}, {%0,%1,%2,%3};" \
        : "+f"((D)[0]), "+f"((D)[1]), "+f"((D)[2]), "+f"((D)[3]) \
        : "r"(A0), "r"(A1), "r"(A2), "r"(A3), "r"(B0), "r"(B1))

__device__ __forceinline__ void cvt_hilo(float4 v, uint2& oh, uint2& ol) {
    __nv_bfloat162 h01 = __floats2bfloat162_rn(v.x, v.y);
    __nv_bfloat162 h23 = __floats2bfloat162_rn(v.z, v.w);
    __nv_bfloat162 l01 = __floats2bfloat162_rn(v.x - __bfloat162float(h01.x),
                                               v.y - __bfloat162float(h01.y));
    __nv_bfloat162 l23 = __floats2bfloat162_rn(v.z - __bfloat162float(h23.x),
                                               v.w - __bfloat162float(h23.y));
    oh.x = *(uint32_t*)&h01; oh.y = *(uint32_t*)&h23;
    ol.x = *(uint32_t*)&l01; ol.y = *(uint32_t*)&l23;
}

__global__ void __launch_bounds__(256) mma_pregate(
    const float* __restrict__ A,     // [M][K] fp32
    const float* __restrict__ W,     // [512][K] fp32
    const float* __restrict__ ba, const float* __restrict__ bb,
    float* __restrict__ C,           // [M][512]
    int K)
{
    extern __shared__ __nv_bfloat16 smem[];
    const int stride = K + 8;
    __nv_bfloat16* sAhi = smem;
    __nv_bfloat16* sAlo = sAhi + 128 * stride;
    __nv_bfloat16* sWhi = sAlo + 128 * stride;
    __nv_bfloat16* sWlo = sWhi + 128 * stride;
    float* sbias = (float*)(sWlo + 128 * stride);

    const int tid = threadIdx.x;
    const int lane = tid & 31;
    const int wid = tid >> 5;
    const int wm = wid & 3;
    const int wn = wid >> 2;
    const int g = lane >> 2;
    const int tig = lane & 3;

    const int m0 = blockIdx.x * 128;
    const int kv = K >> 2;

    for (int i = tid; i < 512; i += 256) sbias[i] = ba[i] + bb[i];

    for (int idx = tid; idx < 128 * kv; idx += 256) {
        int row = idx / kv;
        int q = idx - row * kv;
        float4 v = *(const float4*)(A + (size_t)(m0 + row) * K + q * 4);
        uint2 oh, ol;
        cvt_hilo(v, oh, ol);
        *(uint2*)(&sAhi[row * stride + q * 4]) = oh;
        *(uint2*)(&sAlo[row * stride + q * 4]) = ol;
    }

    for (int nb = 0; nb < 4; nb++) {
        __syncthreads();
        for (int idx = tid; idx < 128 * kv; idx += 256) {
            int row = idx / kv;
            int q = idx - row * kv;
            float4 v = *(const float4*)(W + (size_t)(nb * 128 + row) * K + q * 4);
            uint2 oh, ol;
            cvt_hilo(v, oh, ol);
            *(uint2*)(&sWhi[row * stride + q * 4]) = oh;
            *(uint2*)(&sWlo[row * stride + q * 4]) = ol;
        }
        __syncthreads();

        float d[2][8][4];
        #pragma unroll
        for (int mf = 0; mf < 2; mf++)
            #pragma unroll
            for (int nf = 0; nf < 8; nf++)
                #pragma unroll
                for (int e = 0; e < 4; e++) d[mf][nf][e] = 0.0f;

        const int nks = K >> 4;
        for (int ks = 0; ks < nks; ks++) {
            const int c0 = ks * 16 + 2 * tig;
            const int c1 = c0 + 8;

            uint32_t AH[2][4], AL[2][4];
            #pragma unroll
            for (int mf = 0; mf < 2; mf++) {
                int r0 = (wm * 32 + mf * 16 + g) * stride;
                int r8 = r0 + 8 * stride;
                AH[mf][0] = *(const uint32_t*)(&sAhi[r0 + c0]);
                AH[mf][1] = *(const uint32_t*)(&sAhi[r8 + c0]);
                AH[mf][2] = *(const uint32_t*)(&sAhi[r0 + c1]);
                AH[mf][3] = *(const uint32_t*)(&sAhi[r8 + c1]);
                AL[mf][0] = *(const uint32_t*)(&sAlo[r0 + c0]);
                AL[mf][1] = *(const uint32_t*)(&sAlo[r8 + c0]);
                AL[mf][2] = *(const uint32_t*)(&sAlo[r0 + c1]);
                AL[mf][3] = *(const uint32_t*)(&sAlo[r8 + c1]);
            }
            #pragma unroll
            for (int nf = 0; nf < 8; nf++) {
                int rb = (wn * 64 + nf * 8 + g) * stride;
                uint32_t BH0 = *(const uint32_t*)(&sWhi[rb + c0]);
                uint32_t BH1 = *(const uint32_t*)(&sWhi[rb + c1]);
                uint32_t BL0 = *(const uint32_t*)(&sWlo[rb + c0]);
                uint32_t BL1 = *(const uint32_t*)(&sWlo[rb + c1]);
                #pragma unroll
                for (int mf = 0; mf < 2; mf++) {
                    MMA_BF16(d[mf][nf], AH[mf][0], AH[mf][1], AH[mf][2], AH[mf][3], BH0, BH1);
                    MMA_BF16(d[mf][nf], AL[mf][0], AL[mf][1], AL[mf][2], AL[mf][3], BH0, BH1);
                    MMA_BF16(d[mf][nf], AH[mf][0], AH[mf][1], AH[mf][2], AH[mf][3], BL0, BL1);
                }
            }
        }

        #pragma unroll
        for (int mf = 0; mf < 2; mf++) {
            int r0 = wm * 32 + mf * 16 + g;
            #pragma unroll
            for (int nf = 0; nf < 8; nf++) {
                int nl = nb * 128 + wn * 64 + nf * 8 + 2 * tig;
                float bx = sbias[nl];
                float by = sbias[nl + 1];
                float2 o0, o1;
                o0.x = d[mf][nf][0] + bx; o0.y = d[mf][nf][1] + by;
                o1.x = d[mf][nf][2] + bx; o1.y = d[mf][nf][3] + by;
                *(float2*)(C + (size_t)(m0 + r0) * GG + nl) = o0;
                *(float2*)(C + (size_t)(m0 + r0 + 8) * GG + nl) = o1;
            }
        }
    }
}

// -------- LSTM recurrence: intra-warp k-split, shfl reduction, 1 barrier/step --------
// warp = j-block (8 j), lane = kq*8+js; lane owns (row=kq, j=jb*8+js).
// acc a[r*4+g] f32x2 over (even-k, odd-k); weights layout identical to round 4.

#define MAC4(HV0, HV1, HV2, HV3, W0, W1) { \
    a[0]  = fma2(HV0, W0.x, a[0]);  a[1]  = fma2(HV0, W0.y, a[1]); \
    a[2]  = fma2(HV0, W1.x, a[2]);  a[3]  = fma2(HV0, W1.y, a[3]); \
    a[4]  = fma2(HV1, W0.x, a[4]);  a[5]  = fma2(HV1, W0.y, a[5]); \
    a[6]  = fma2(HV1, W1.x, a[6]);  a[7]  = fma2(HV1, W1.y, a[7]); \
    a[8]  = fma2(HV2, W0.x, a[8]);  a[9]  = fma2(HV2, W0.y, a[9]); \
    a[10] = fma2(HV2, W1.x, a[10]); a[11] = fma2(HV2, W1.y, a[11]); \
    a[12] = fma2(HV3, W0.x, a[12]); a[13] = fma2(HV3, W0.y, a[13]); \
    a[14] = fma2(HV3, W1.x, a[14]); a[15] = fma2(HV3, W1.y, a[15]); }

__global__ void __launch_bounds__(512, 1) lstm_layer_kernel(
    const float* __restrict__ xg,
    const float* __restrict__ WTI,
    float* __restrict__ hout,
    float* __restrict__ hlast)
{
    extern __shared__ float sm[];
    const ulonglong2* swA = (const ulonglong2*)sm;     // 48 kp x 128 j (16B each)
    const ulonglong2* swB = swA + 6144;
    float* shbuf = sm + 49152;                          // [2][4][128]

    const int tid = threadIdx.x;
    const int lane = tid & 31;
    const int jb = tid >> 5;            // warp id = j block
    const int kq = lane >> 3;           // k quarter AND owned row
    const int js = lane & 7;
    const int j = jb * 8 + js;
    const int b0 = blockIdx.x * 4;

    // load weights kp [0,48) of both regions into smem
    {
        const float4* g4 = (const float4*)WTI;
        float4* s4 = (float4*)sm;
        #pragma unroll 4
        for (int i = tid; i < 6144; i += 512) s4[i] = g4[i];
        #pragma unroll 4
        for (int i = tid; i < 6144; i += 512) s4[6144 + i] = g4[8192 + i];
    }
    // reg tail: kp [48 + kq*4, +4)
    ulonglong2 wtA[4], wtB[4];
    {
        const ulonglong2* gA = (const ulonglong2*)WTI;
        const ulonglong2* gB = gA + 8192;
        int kt = KPSM + kq * 4;
        #pragma unroll
        for (int i = 0; i < 4; i++) {
            wtA[i] = gA[(size_t)(kt + i) * 128 + j];
            wtB[i] = gB[(size_t)(kt + i) * 128 + j];
        }
    }
    shbuf[tid] = 0.0f;
    shbuf[tid + 512] = 0.0f;

    const size_t xbase = ((size_t)(b0 + kq)) * TT * GG + j;
    float* houtP = hout ? hout + ((size_t)(b0 + kq)) * TT * HH + j : (float*)0;

    float xc0 = xg[xbase], xc1 = xg[xbase + 128], xc2 = xg[xbase + 256], xc3 = xg[xbase + 384];

    const bool lowpair = (kq < 2);
    const bool evenq = ((kq & 1) == 0);

    float cc = 0.0f, hh = 0.0f;
    __syncthreads();

    for (int t = 0; t < TT; t++) {
        const float* shr = shbuf + (t & 1) * 512;
        float* shw = shbuf + ((t & 1) ^ 1) * 512;

        ull a[16];
        #pragma unroll
        for (int i = 0; i < 16; i++) a[i] = 0ULL;

        float xn0 = 0, xn1 = 0, xn2 = 0, xn3 = 0;
        if (t + 1 < TT) {
            size_t o = xbase + (size_t)(t + 1) * GG;
            xn0 = xg[o]; xn1 = xg[o + 128]; xn2 = xg[o + 256]; xn3 = xg[o + 384];
        }

        // smem k range: 12 kp = 24 k (6 groups of 2 kp)
        #pragma unroll
        for (int g = 0; g < 6; g++) {
            int kp0 = kq * 12 + g * 2;
            int kk = kq * 24 + g * 4;
            ulonglong2 H0 = *(const ulonglong2*)(shr + kk);
            ulonglong2 H1 = *(const ulonglong2*)(shr + 128 + kk);
            ulonglong2 H2 = *(const ulonglong2*)(shr + 256 + kk);
            ulonglong2 H3 = *(const ulonglong2*)(shr + 384 + kk);
            ulonglong2 w0 = swA[kp0 * 128 + j];
            ulonglong2 w1 = swB[kp0 * 128 + j];
            MAC4(H0.x, H1.x, H2.x, H3.x, w0, w1);
            ulonglong2 w2 = swA[(kp0 + 1) * 128 + j];
            ulonglong2 w3 = swB[(kp0 + 1) * 128 + j];
            MAC4(H0.y, H1.y, H2.y, H3.y, w2, w3);
        }
        // reg tail: 4 kp = 8 k (2 groups)
        #pragma unroll
        for (int g = 0; g < 2; g++) {
            int kk = 96 + kq * 8 + g * 4;
            ulonglong2 H0 = *(const ulonglong2*)(shr + kk);
            ulonglong2 H1 = *(const ulonglong2*)(shr + 128 + kk);
            ulonglong2 H2 = *(const ulonglong2*)(shr + 256 + kk);
            ulonglong2 H3 = *(const ulonglong2*)(shr + 384 + kk);
            MAC4(H0.x, H1.x, H2.x, H3.x, wtA[g * 2], wtB[g * 2]);
            MAC4(H0.y, H1.y, H2.y, H3.y, wtA[g * 2 + 1], wtB[g * 2 + 1]);
        }

        // intra-warp reduction over kq (2 butterfly rounds, no barrier)
        // round 1: xor 16 (kq^2); low pair keeps rows{0,1}, high pair rows{2,3}
        #pragma unroll
        for (int i = 0; i < 8; i++) {
            ull send = lowpair ? a[8 + i] : a[i];
            ull recv = __shfl_xor_sync(0xFFFFFFFFu, send, 16);
            if (lowpair) a[i] = add2(a[i], recv);
            else         a[8 + i] = add2(a[8 + i], recv);
        }
        ull b[8];
        #pragma unroll
        for (int i = 0; i < 8; i++) b[i] = lowpair ? a[i] : a[8 + i];
        // round 2: xor 8 (kq^1); even kq keeps first row of pair, odd the second
        #pragma unroll
        for (int i = 0; i < 4; i++) {
            ull send = evenq ? b[4 + i] : b[i];
            ull recv = __shfl_xor_sync(0xFFFFFFFFu, send, 8);
            if (evenq) b[i] = add2(b[i], recv);
            else       b[4 + i] = add2(b[4 + i], recv);
        }
        ull f0 = evenq ? b[0] : b[4];
        ull f1 = evenq ? b[1] : b[5];
        ull f2 = evenq ? b[2] : b[6];
        ull f3 = evenq ? b[3] : b[7];

        // activation for owned row (= kq)
        float gi = red2(f0) + xc0;
        float gf = red2(f1) + xc1;
        float gg2 = red2(f2) + xc2;
        float go = red2(f3) + xc3;

        float ii = sigf(gi), ff = sigf(gf), g = tanhx(gg2), oo = sigf(go);
        cc = ff * cc + ii * g;
        hh = oo * tanhx(cc);

        shw[kq * 128 + j] = hh;
        if (hout) houtP[(size_t)t * HH] = hh;

        xc0 = xn0; xc1 = xn1; xc2 = xn2; xc3 = xn3;
        __syncthreads();
    }

    if (hlast) hlast[(b0 + kq) * HH + j] = hh;
}

// -------- MLP head --------
__device__ __forceinline__ float celuf(float x) { return x > 0.0f ? x : expm1f(x); }

__global__ void __launch_bounds__(256) head_kernel(
    const float* __restrict__ hlast,
    const float* __restrict__ W1, const float* __restrict__ b1,
    const float* __restrict__ W2, const float* __restrict__ b2,
    float* __restrict__ out)
{
    const int b = blockIdx.x;
    const int tid = threadIdx.x;
    __shared__ float sl[HH];
    __shared__ float sy[DLL];

    if (tid < HH) sl[tid] = hlast[b * HH + tid];
    __syncthreads();

    float s = b1[tid];
    const float* w = W1 + (size_t)tid * HH;
    #pragma unroll 8
    for (int k = 0; k < HH; k++) s += sl[k] * w[k];
    sy[tid] = celuf(s);
    __syncthreads();

    if (tid < OUTD) {
        float s2 = b2[tid];
        const float* w2 = W2 + (size_t)tid * DLL;
        #pragma unroll 8
        for (int k = 0; k < DLL; k++) s2 += sy[k] * w2[k];
        out[b * OUTD + tid] = celuf(s2);
    }
}

__global__ void zero_tail(float* __restrict__ p, int n) {
    int i = blockIdx.x * 256 + threadIdx.x;
    if (i < n) p[i] = 0.0f;
}

// -------- launch --------
extern "C" void kernel_launch(void* const* d_in, const int* in_sizes, int n_in,
                              void* d_out, int out_size)
{
    const float* x    = (const float*)d_in[0];
    const float* Wih0 = (const float*)d_in[1];
    const float* Whh0 = (const float*)d_in[2];
    const float* bih0 = (const float*)d_in[3];
    const float* bhh0 = (const float*)d_in[4];
    const float* Wih1 = (const float*)d_in[5];
    const float* Whh1 = (const float*)d_in[6];
    const float* bih1 = (const float*)d_in[7];
    const float* bhh1 = (const float*)d_in[8];
    const float* W1   = (const float*)d_in[9];
    const float* b1   = (const float*)d_in[10];
    const float* W2   = (const float*)d_in[11];
    const float* b2   = (const float*)d_in[12];
    float* out = (float*)d_out;

    float *xgp, *h0p, *hlastp, *wt0p, *wt1p;
    cudaGetSymbolAddress((void**)&xgp,    g_xg);
    cudaGetSymbolAddress((void**)&h0p,    g_h0);
    cudaGetSymbolAddress((void**)&hlastp, g_hlast);
    cudaGetSymbolAddress((void**)&wt0p,   g_WT0);
    cudaGetSymbolAddress((void**)&wt1p,   g_WT1);

    const int smem_k128 = 4 * 128 * (HH + 8) * 2 + 512 * 4;
    const int smem_k32  = 4 * 128 * (INDIM + 8) * 2 + 512 * 4;

    cudaFuncSetAttribute(lstm_layer_kernel, cudaFuncAttributeMaxDynamicSharedMemorySize, LSTM_SMEM);
    cudaFuncSetAttribute(mma_pregate,       cudaFuncAttributeMaxDynamicSharedMemorySize, smem_k128);

    prep_whh<<<256, 256>>>(Whh0, wt0p);
    prep_whh<<<256, 256>>>(Whh1, wt1p);

    // layer 0: pre-gates (mma.sync bf16 split, K=32) then recurrence
    mma_pregate<<<M_TOT / 128, 256, smem_k32>>>(x, Wih0, bih0, bhh0, xgp, INDIM);
    lstm_layer_kernel<<<BB / 4, 512, LSTM_SMEM>>>(xgp, wt0p, h0p, nullptr);

    // layer 1: pre-gates (mma.sync bf16 split, K=128) then recurrence
    mma_pregate<<<M_TOT / 128, 256, smem_k128>>>(h0p, Wih1, bih1, bhh1, xgp, HH);
    lstm_layer_kernel<<<BB / 4, 512, LSTM_SMEM>>>(xgp, wt1p, nullptr, hlastp);

    head_kernel<<<BB, 256>>>(hlastp, W1, b1, W2, b2, out);
    int tail = out_size - BB * OUTD;
    if (tail > 0)
        zero_tail<<<(tail + 255) / 256, 256>>>(out + BB * OUTD, tail);
}

// round 10
// speedup vs baseline: 1.1142x; 1.1142x over previous
#include <cuda_runtime.h>
#include <cuda_bf16.h>
#include <cstdint>
#include <cstddef>

typedef unsigned long long ull;

#define BB 512
#define TT 1024
#define INDIM 32
#define HH 128
#define GG 512            // 4*H
#define DLL 256
#define OUTD 32
#define M_TOT (BB*TT)     // 524288

// ---- lstm smem layout (round-4/7, proven) ----
#define KPSM 48
#define LSTM_SMEM ((49152 + 512 + 6144) * 4)    // 223232 bytes

// -------- device scratch (static; no runtime allocation) --------
__device__ float g_xg[(size_t)M_TOT * GG];
__device__ float g_h0[(size_t)M_TOT * HH];
__device__ float g_hlast[BB * HH];
__device__ float g_WT0[HH * GG];
__device__ float g_WT1[HH * GG];

// ---------------- f32x2 helpers (lstm) ----------------
__device__ __forceinline__ ull fma2(ull a, ull b, ull c) {
    ull d;
    asm("fma.rn.f32x2 %0, %1, %2, %3;" : "=l"(d) : "l"(a), "l"(b), "l"(c));
    return d;
}
__device__ __forceinline__ void unpack2(ull v, float& x, float& y) {
    unsigned a, b;
    asm("mov.b64 {%0, %1}, %2;" : "=r"(a), "=r"(b) : "l"(v));
    x = __uint_as_float(a);
    y = __uint_as_float(b);
}
__device__ __forceinline__ float red2(ull v) {
    float a, b;
    unpack2(v, a, b);
    return a + b;
}
__device__ __forceinline__ float sigf(float x)  { return __fdividef(1.0f, 1.0f + __expf(-x)); }
__device__ __forceinline__ float tanhx(float x) { return __fdividef(2.0f, 1.0f + __expf(-2.0f * x)) - 1.0f; }

// -------- interleave Whh for lstm (unchanged) --------
__global__ void prep_whh(const float* __restrict__ W, float* __restrict__ WTI) {
    int idx = blockIdx.x * 256 + threadIdx.x;
    if (idx < HH * GG) {
        int r = idx >> 15;
        int rem = idx & 32767;
        int kp = rem >> 9;
        int rem2 = rem & 511;
        int j = rem2 >> 2;
        int t = rem2 & 3;
        int qq = t >> 1;
        int e = t & 1;
        int q = r * 2 + qq;
        WTI[idx] = W[(q * HH + j) * HH + 2 * kp + e];
    }
}

// ================= mma.sync bf16 hi/lo pre-gate GEMM =================
// C[m][n] = sum_k A[m][k]*W[n][k] + ba[n] + bb[n]
// grid (M/128): A tile converted once per CTA; 8 N-blocks of 64 rows of W,
// smem 104 KB -> 2 CTAs/SM. 8 warps: warp tile 32m x 32n.
// 3-MMA split: Ahi*Whi + Alo*Whi + Ahi*Wlo.

#define MMA_BF16(D, A0, A1, A2, A3, B0, B1) \
    asm volatile( \
        "mma.sync.aligned.m16n8k16.row.col.f32.bf16.bf16.f32 " \
        "{%0,%1,%2,%3}, {%4,%5,%6,%7}, {%8,%9}, {%0,%1,%2,%3};" \
        : "+f"((D)[0]), "+f"((D)[1]), "+f"((D)[2]), "+f"((D)[3]) \
        : "r"(A0), "r"(A1), "r"(A2), "r"(A3), "r"(B0), "r"(B1))

__device__ __forceinline__ void cvt_hilo(float4 v, uint2& oh, uint2& ol) {
    __nv_bfloat162 h01 = __floats2bfloat162_rn(v.x, v.y);
    __nv_bfloat162 h23 = __floats2bfloat162_rn(v.z, v.w);
    __nv_bfloat162 l01 = __floats2bfloat162_rn(v.x - __bfloat162float(h01.x),
                                               v.y - __bfloat162float(h01.y));
    __nv_bfloat162 l23 = __floats2bfloat162_rn(v.z - __bfloat162float(h23.x),
                                               v.w - __bfloat162float(h23.y));
    oh.x = *(uint32_t*)&h01; oh.y = *(uint32_t*)&h23;
    ol.x = *(uint32_t*)&l01; ol.y = *(uint32_t*)&l23;
}

__global__ void __launch_bounds__(256, 2) mma_pregate(
    const float* __restrict__ A,     // [M][K] fp32
    const float* __restrict__ W,     // [512][K] fp32
    const float* __restrict__ ba, const float* __restrict__ bb,
    float* __restrict__ C,           // [M][512]
    int K)
{
    extern __shared__ __nv_bfloat16 smem[];
    const int stride = K + 8;
    __nv_bfloat16* sAhi = smem;
    __nv_bfloat16* sAlo = sAhi + 128 * stride;
    __nv_bfloat16* sWhi = sAlo + 128 * stride;
    __nv_bfloat16* sWlo = sWhi + 64 * stride;
    float* sbias = (float*)(sWlo + 64 * stride);

    const int tid = threadIdx.x;
    const int lane = tid & 31;
    const int wid = tid >> 5;
    const int wm = wid & 3;              // warp m index: rows wm*32 .. +32
    const int wn = wid >> 2;             // warp n index: cols wn*32 .. +32
    const int g = lane >> 2;
    const int tig = lane & 3;

    const int m0 = blockIdx.x * 128;
    const int kv = K >> 2;

    for (int i = tid; i < 512; i += 256) sbias[i] = ba[i] + bb[i];

    // convert A tile once: 128 rows x K
    for (int idx = tid; idx < 128 * kv; idx += 256) {
        int row = idx / kv;
        int q = idx - row * kv;
        float4 v = *(const float4*)(A + (size_t)(m0 + row) * K + q * 4);
        uint2 oh, ol;
        cvt_hilo(v, oh, ol);
        *(uint2*)(&sAhi[row * stride + q * 4]) = oh;
        *(uint2*)(&sAlo[row * stride + q * 4]) = ol;
    }

    for (int nb = 0; nb < 8; nb++) {
        __syncthreads();   // prior mma done reading W (and A ready at nb=0)
        // convert W block: rows nb*64 .. +64
        for (int idx = tid; idx < 64 * kv; idx += 256) {
            int row = idx / kv;
            int q = idx - row * kv;
            float4 v = *(const float4*)(W + (size_t)(nb * 64 + row) * K + q * 4);
            uint2 oh, ol;
            cvt_hilo(v, oh, ol);
            *(uint2*)(&sWhi[row * stride + q * 4]) = oh;
            *(uint2*)(&sWlo[row * stride + q * 4]) = ol;
        }
        __syncthreads();

        float d[2][4][4];
        #pragma unroll
        for (int mf = 0; mf < 2; mf++)
            #pragma unroll
            for (int nf = 0; nf < 4; nf++)
                #pragma unroll
                for (int e = 0; e < 4; e++) d[mf][nf][e] = 0.0f;

        const int nks = K >> 4;
        for (int ks = 0; ks < nks; ks++) {
            const int c0 = ks * 16 + 2 * tig;
            const int c1 = c0 + 8;

            uint32_t AH[2][4], AL[2][4];
            #pragma unroll
            for (int mf = 0; mf < 2; mf++) {
                int r0 = (wm * 32 + mf * 16 + g) * stride;
                int r8 = r0 + 8 * stride;
                AH[mf][0] = *(const uint32_t*)(&sAhi[r0 + c0]);
                AH[mf][1] = *(const uint32_t*)(&sAhi[r8 + c0]);
                AH[mf][2] = *(const uint32_t*)(&sAhi[r0 + c1]);
                AH[mf][3] = *(const uint32_t*)(&sAhi[r8 + c1]);
                AL[mf][0] = *(const uint32_t*)(&sAlo[r0 + c0]);
                AL[mf][1] = *(const uint32_t*)(&sAlo[r8 + c0]);
                AL[mf][2] = *(const uint32_t*)(&sAlo[r0 + c1]);
                AL[mf][3] = *(const uint32_t*)(&sAlo[r8 + c1]);
            }
            #pragma unroll
            for (int nf = 0; nf < 4; nf++) {
                int rb = (wn * 32 + nf * 8 + g) * stride;
                uint32_t BH0 = *(const uint32_t*)(&sWhi[rb + c0]);
                uint32_t BH1 = *(const uint32_t*)(&sWhi[rb + c1]);
                uint32_t BL0 = *(const uint32_t*)(&sWlo[rb + c0]);
                uint32_t BL1 = *(const uint32_t*)(&sWlo[rb + c1]);
                #pragma unroll
                for (int mf = 0; mf < 2; mf++) {
                    MMA_BF16(d[mf][nf], AH[mf][0], AH[mf][1], AH[mf][2], AH[mf][3], BH0, BH1);
                    MMA_BF16(d[mf][nf], AL[mf][0], AL[mf][1], AL[mf][2], AL[mf][3], BH0, BH1);
                    MMA_BF16(d[mf][nf], AH[mf][0], AH[mf][1], AH[mf][2], AH[mf][3], BL0, BL1);
                }
            }
        }

        // epilogue: add bias, store float2 pairs
        #pragma unroll
        for (int mf = 0; mf < 2; mf++) {
            int r0 = wm * 32 + mf * 16 + g;
            #pragma unroll
            for (int nf = 0; nf < 4; nf++) {
                int nl = nb * 64 + wn * 32 + nf * 8 + 2 * tig;
                float bx = sbias[nl];
                float by = sbias[nl + 1];
                float2 o0, o1;
                o0.x = d[mf][nf][0] + bx; o0.y = d[mf][nf][1] + by;
                o1.x = d[mf][nf][2] + bx; o1.y = d[mf][nf][3] + by;
                *(float2*)(C + (size_t)(m0 + r0) * GG + nl) = o0;
                *(float2*)(C + (size_t)(m0 + r0 + 8) * GG + nl) = o1;
            }
        }
    }
}

// -------- LSTM recurrence (round-4/7, proven — FROZEN) --------
#define MAC4(HV0, HV1, HV2, HV3, W0, W1) { \
    a00 = fma2(HV0, W0.x, a00); a01 = fma2(HV0, W0.y, a01); \
    a02 = fma2(HV0, W1.x, a02); a03 = fma2(HV0, W1.y, a03); \
    a10 = fma2(HV1, W0.x, a10); a11 = fma2(HV1, W0.y, a11); \
    a12 = fma2(HV1, W1.x, a12); a13 = fma2(HV1, W1.y, a13); \
    a20 = fma2(HV2, W0.x, a20); a21 = fma2(HV2, W0.y, a21); \
    a22 = fma2(HV2, W1.x, a22); a23 = fma2(HV2, W1.y, a23); \
    a30 = fma2(HV3, W0.x, a30); a31 = fma2(HV3, W0.y, a31); \
    a32 = fma2(HV3, W1.x, a32); a33 = fma2(HV3, W1.y, a33); }

__global__ void __launch_bounds__(512, 1) lstm_layer_kernel(
    const float* __restrict__ xg,
    const float* __restrict__ WTI,
    float* __restrict__ hout,
    float* __restrict__ hlast)
{
    extern __shared__ float sm[];
    const ulonglong2* swA = (const ulonglong2*)sm;
    const ulonglong2* swB = swA + 6144;
    float* sh = sm + 49152;
    float4* sxf = (float4*)(sm + 49152 + 512);

    const int tid = threadIdx.x;
    const int j = tid & 127;
    const int u = tid >> 7;
    const int b0 = blockIdx.x * 4;

    {
        const float4* g4 = (const float4*)WTI;
        float4* s4 = (float4*)sm;
        #pragma unroll 4
        for (int i = tid; i < 6144; i += 512) s4[i] = g4[i];
        #pragma unroll 4
        for (int i = tid; i < 6144; i += 512) s4[6144 + i] = g4[8192 + i];
    }
    ulonglong2 wtA[4], wtB[4];
    {
        const ulonglong2* gA = (const ulonglong2*)WTI;
        const ulonglong2* gB = gA + 8192;
        int kt = KPSM + u * 4;
        #pragma unroll
        for (int i = 0; i < 4; i++) {
            wtA[i] = gA[(size_t)(kt + i) * 128 + j];
            wtB[i] = gB[(size_t)(kt + i) * 128 + j];
        }
    }
    sh[tid] = 0.0f;

    const int klo = u * 24;
    const int kplo = u * 12;

    const size_t xbase = ((size_t)(b0 + u)) * TT * GG + j;
    float* houtP = hout ? hout + ((size_t)(b0 + u)) * TT * HH + j : (float*)0;

    float xc0 = xg[xbase], xc1 = xg[xbase + 128], xc2 = xg[xbase + 256], xc3 = xg[xbase + 384];

    float cc = 0.0f, hh = 0.0f;
    __syncthreads();

    for (int t = 0; t < TT; t++) {
        ull a00 = 0, a01 = 0, a02 = 0, a03 = 0;
        ull a10 = 0, a11 = 0, a12 = 0, a13 = 0;
        ull a20 = 0, a21 = 0, a22 = 0, a23 = 0;
        ull a30 = 0, a31 = 0, a32 = 0, a33 = 0;

        float xn0 = 0, xn1 = 0, xn2 = 0, xn3 = 0;
        if (t + 1 < TT) {
            size_t o = xbase + (size_t)(t + 1) * GG;
            xn0 = xg[o]; xn1 = xg[o + 128]; xn2 = xg[o + 256]; xn3 = xg[o + 384];
        }

        #pragma unroll
        for (int g = 0; g < 6; g++) {
            int kb = klo + g * 4;
            ulonglong2 H0 = *(const ulonglong2*)(sh + kb);
            ulonglong2 H1 = *(const ulonglong2*)(sh + 128 + kb);
            ulonglong2 H2 = *(const ulonglong2*)(sh + 256 + kb);
            ulonglong2 H3 = *(const ulonglong2*)(sh + 384 + kb);
            int kpi = (kplo + g * 2) * 128 + j;
            ulonglong2 w0 = swA[kpi];
            ulonglong2 w1 = swB[kpi];
            MAC4(H0.x, H1.x, H2.x, H3.x, w0, w1);
            ulonglong2 w2 = swA[kpi + 128];
            ulonglong2 w3 = swB[kpi + 128];
            MAC4(H0.y, H1.y, H2.y, H3.y, w2, w3);
        }
        #pragma unroll
        for (int g = 0; g < 2; g++) {
            int kb = 96 + u * 8 + g * 4;
            ulonglong2 H0 = *(const ulonglong2*)(sh + kb);
            ulonglong2 H1 = *(const ulonglong2*)(sh + 128 + kb);
            ulonglong2 H2 = *(const ulonglong2*)(sh + 256 + kb);
            ulonglong2 H3 = *(const ulonglong2*)(sh + 384 + kb);
            MAC4(H0.x, H1.x, H2.x, H3.x, wtA[g * 2], wtB[g * 2]);
            MAC4(H0.y, H1.y, H2.y, H3.y, wtA[g * 2 + 1], wtB[g * 2 + 1]);
        }

        float4 s0, s1, s2, s3;
        s0.x = red2(a00); s0.y = red2(a01); s0.z = red2(a02); s0.w = red2(a03);
        s1.x = red2(a10); s1.y = red2(a11); s1.z = red2(a12); s1.w = red2(a13);
        s2.x = red2(a20); s2.y = red2(a21); s2.z = red2(a22); s2.w = red2(a23);
        s3.x = red2(a30); s3.y = red2(a31); s3.z = red2(a32); s3.w = red2(a33);

        if (u != 0) sxf[(0 * 3 + (u - 1)) * 128 + j] = s0;
        if (u != 1) sxf[(1 * 3 + ((u == 0) ? 0 : u - 1)) * 128 + j] = s1;
        if (u != 2) sxf[(2 * 3 + ((u == 3) ? 2 : u)) * 128 + j] = s2;
        if (u != 3) sxf[(3 * 3 + u) * 128 + j] = s3;
        __syncthreads();
        {
            float4 own = (u == 0) ? s0 : (u == 1) ? s1 : (u == 2) ? s2 : s3;
            float4 p0 = sxf[u * 384 + j];
            float4 p1 = sxf[u * 384 + 128 + j];
            float4 p2 = sxf[u * 384 + 256 + j];
            float gi = own.x + xc0 + p0.x + p1.x + p2.x;
            float gf = own.y + xc1 + p0.y + p1.y + p2.y;
            float gg2 = own.z + xc2 + p0.z + p1.z + p2.z;
            float go = own.w + xc3 + p0.w + p1.w + p2.w;

            float ii = sigf(gi), ff = sigf(gf), g = tanhx(gg2), oo = sigf(go);
            cc = ff * cc + ii * g;
            hh = oo * tanhx(cc);

            sh[u * 128 + j] = hh;
            if (hout) houtP[(size_t)t * HH] = hh;
        }
        xc0 = xn0; xc1 = xn1; xc2 = xn2; xc3 = xn3;
        __syncthreads();
    }

    if (hlast) hlast[(b0 + u) * HH + j] = hh;
}

// -------- MLP head --------
__device__ __forceinline__ float celuf(float x) { return x > 0.0f ? x : expm1f(x); }

__global__ void __launch_bounds__(256) head_kernel(
    const float* __restrict__ hlast,
    const float* __restrict__ W1, const float* __restrict__ b1,
    const float* __restrict__ W2, const float* __restrict__ b2,
    float* __restrict__ out)
{
    const int b = blockIdx.x;
    const int tid = threadIdx.x;
    __shared__ float sl[HH];
    __shared__ float sy[DLL];

    if (tid < HH) sl[tid] = hlast[b * HH + tid];
    __syncthreads();

    float s = b1[tid];
    const float* w = W1 + (size_t)tid * HH;
    #pragma unroll 8
    for (int k = 0; k < HH; k++) s += sl[k] * w[k];
    sy[tid] = celuf(s);
    __syncthreads();

    if (tid < OUTD) {
        float s2 = b2[tid];
        const float* w2 = W2 + (size_t)tid * DLL;
        #pragma unroll 8
        for (int k = 0; k < DLL; k++) s2 += sy[k] * w2[k];
        out[b * OUTD + tid] = celuf(s2);
    }
}

__global__ void zero_tail(float* __restrict__ p, int n) {
    int i = blockIdx.x * 256 + threadIdx.x;
    if (i < n) p[i] = 0.0f;
}

// -------- launch --------
extern "C" void kernel_launch(void* const* d_in, const int* in_sizes, int n_in,
                              void* d_out, int out_size)
{
    const float* x    = (const float*)d_in[0];
    const float* Wih0 = (const float*)d_in[1];
    const float* Whh0 = (const float*)d_in[2];
    const float* bih0 = (const float*)d_in[3];
    const float* bhh0 = (const float*)d_in[4];
    const float* Wih1 = (const float*)d_in[5];
    const float* Whh1 = (const float*)d_in[6];
    const float* bih1 = (const float*)d_in[7];
    const float* bhh1 = (const float*)d_in[8];
    const float* W1   = (const float*)d_in[9];
    const float* b1   = (const float*)d_in[10];
    const float* W2   = (const float*)d_in[11];
    const float* b2   = (const float*)d_in[12];
    float* out = (float*)d_out;

    float *xgp, *h0p, *hlastp, *wt0p, *wt1p;
    cudaGetSymbolAddress((void**)&xgp,    g_xg);
    cudaGetSymbolAddress((void**)&h0p,    g_h0);
    cudaGetSymbolAddress((void**)&hlastp, g_hlast);
    cudaGetSymbolAddress((void**)&wt0p,   g_WT0);
    cudaGetSymbolAddress((void**)&wt1p,   g_WT1);

    // dynamic smem: A(2x128xstride) + W(2x64xstride) bf16 + 512-float bias
    const int smem_k128 = (2 * 128 * (HH + 8) + 2 * 64 * (HH + 8)) * 2 + 512 * 4;      // 106496
    const int smem_k32  = (2 * 128 * (INDIM + 8) + 2 * 64 * (INDIM + 8)) * 2 + 512 * 4; // 32768

    cudaFuncSetAttribute(lstm_layer_kernel, cudaFuncAttributeMaxDynamicSharedMemorySize, LSTM_SMEM);
    cudaFuncSetAttribute(mma_pregate,       cudaFuncAttributeMaxDynamicSharedMemorySize, smem_k128);

    prep_whh<<<256, 256>>>(Whh0, wt0p);
    prep_whh<<<256, 256>>>(Whh1, wt1p);

    // layer 0: pre-gates (mma.sync bf16 split, K=32) then recurrence
    mma_pregate<<<M_TOT / 128, 256, smem_k32>>>(x, Wih0, bih0, bhh0, xgp, INDIM);
    lstm_layer_kernel<<<BB / 4, 512, LSTM_SMEM>>>(xgp, wt0p, h0p, nullptr);

    // layer 1: pre-gates (mma.sync bf16 split, K=128) then recurrence
    mma_pregate<<<M_TOT / 128, 256, smem_k128>>>(h0p, Wih1, bih1, bhh1, xgp, HH);
    lstm_layer_kernel<<<BB / 4, 512, LSTM_SMEM>>>(xgp, wt1p, nullptr, hlastp);

    head_kernel<<<BB, 256>>>(hlastp, W1, b1, W2, b2, out);
    int tail = out_size - BB * OUTD;
    if (tail > 0)
        zero_tail<<<(tail + 255) / 256, 256>>>(out + BB * OUTD, tail);
}